// round 11
// baseline (speedup 1.0000x reference)
#include <cuda_runtime.h>
#include <cuda_fp16.h>
#include <math.h>

#define NN 2000   // nodes
#define HH 512    // hidden
#define DD 256    // embed dim
#define RR 86     // relations
#define EMAX 200000

// Scratch
__device__ float  g_fpn[NN * HH];
__device__ __half g_P[NN * 4 * DD];     // per node: [x1 | x2 | xfp | xskip] (fp16)
__device__ __half g_wAB[RR * 2 * DD];   // per relation: [wr-wi | wr+wi] (fp16)
__device__ float  g_NS[NN * 8];         // per node: S[4]
__device__ float  g_RS[RR * 2];         // per relation: sum(wA), sum(wB)
__device__ int    g_cnt[NN];            // histogram of idx1
__device__ int    g_cur[NN];            // running offsets (rewritten by scan each call)
__device__ int    g_perm[EMAX];         // edge order sorted by idx1

__device__ __forceinline__ float elu1(float x) {
    return x > 0.f ? x : expm1f(x);
}
__device__ __forceinline__ float sum4(const float4& v) {
    return (v.x + v.y) + (v.z + v.w);
}
__device__ __forceinline__ float sq4(const float4& v) {
    float q = v.x * v.x;
    q = fmaf(v.y, v.y, q);
    q = fmaf(v.z, v.z, q);
    q = fmaf(v.w, v.w, q);
    return q;
}
__device__ __forceinline__ void cvt8(const float4& r, float* f) {
    const __half2* h = reinterpret_cast<const __half2*>(&r);
#pragma unroll
    for (int i = 0; i < 4; ++i) {
        float2 t = __half22float2(h[i]);
        f[2 * i]     = t.x;
        f[2 * i + 1] = t.y;
    }
}
__device__ __forceinline__ __half2 h2(const float4& r, int k) {
    return reinterpret_cast<const __half2*>(&r)[k];
}
__device__ __forceinline__ void comb4(const float4& ra, const float4& rb,
                                      __half2* o, float& q) {
#pragma unroll
    for (int k = 0; k < 4; ++k) {
        __half2 s = __hadd2(h2(ra, k), h2(rb, k));
        o[k] = s;
        float2 t = __half22float2(s);
        q = fmaf(t.x, t.x, q);
        q = fmaf(t.y, t.y, q);
    }
}

// ---------------------------------------------------------------------------
// Kernel 1: fp_n = elu(LayerNorm(drug_fp)), one warp per row (H=512)
// ---------------------------------------------------------------------------
__global__ void lnelu512_kernel(const float* __restrict__ in, float* __restrict__ out) {
    int gw   = (blockIdx.x * blockDim.x + threadIdx.x) >> 5;
    int lane = threadIdx.x & 31;
    if (gw >= NN) return;
    const float4* p = reinterpret_cast<const float4*>(in + (size_t)gw * HH);
    float4 v[4];
    float s = 0.f, q = 0.f;
#pragma unroll
    for (int i = 0; i < 4; ++i) {
        v[i] = p[lane + 32 * i];
        s += sum4(v[i]);
        q += sq4(v[i]);
    }
#pragma unroll
    for (int o = 16; o; o >>= 1) {
        s += __shfl_xor_sync(0xffffffffu, s, o);
        q += __shfl_xor_sync(0xffffffffu, q, o);
    }
    float m   = s * (1.f / HH);
    float var = fmaf(-m, m, q * (1.f / HH));
    float inv = rsqrtf(var + 1e-5f);
    float4* o4 = reinterpret_cast<float4*>(out + (size_t)gw * HH);
#pragma unroll
    for (int i = 0; i < 4; ++i) {
        float4 y;
        y.x = elu1((v[i].x - m) * inv);
        y.y = elu1((v[i].y - m) * inv);
        y.z = elu1((v[i].z - m) * inv);
        y.w = elu1((v[i].w - m) * inv);
        o4[lane + 32 * i] = y;
    }
}

// ---------------------------------------------------------------------------
// Kernel 2: pack x1/x2 into P (fp16), precombine relation weights (fp16)
// ---------------------------------------------------------------------------
__global__ void pack_kernel(const float* __restrict__ x1, const float* __restrict__ x2,
                            const float* __restrict__ wr, const float* __restrict__ wi,
                            __half* __restrict__ P, __half* __restrict__ wAB) {
    int i = blockIdx.x * blockDim.x + threadIdx.x;
    if (i < NN * DD) {
        int n = i >> 8, d = i & 255;
        P[(size_t)n * (4 * DD) + d]      = __float2half(x1[i]);
        P[(size_t)n * (4 * DD) + DD + d] = __float2half(x2[i]);
    }
    if (i < RR * DD) {
        int r = i >> 8, d = i & 255;
        float a = wr[i], b = wi[i];
        wAB[(size_t)r * (2 * DD) + d]      = __float2half(a - b);
        wAB[(size_t)r * (2 * DD) + DD + d] = __float2half(a + b);
    }
}

// ---------------------------------------------------------------------------
// Kernel 3: GEMM C[n,slot,d] = (elu?)(sum_h A[n,h] * W[d,h]) -> fp16 into P
// ---------------------------------------------------------------------------
__global__ void __launch_bounds__(256)
gemm_nt_kernel(const float* __restrict__ A0, const float* __restrict__ W0,
               const float* __restrict__ A1, const float* __restrict__ W1,
               __half* __restrict__ P) {
    __shared__ float As[16][65];
    __shared__ float Ws[16][65];
    const float* A = blockIdx.z ? A1 : A0;
    const float* W = blockIdx.z ? W1 : W0;
    int slot = blockIdx.z ? 3 : 2;
    int doElu = blockIdx.z ? 0 : 1;
    int tid = threadIdx.x;
    int tx = tid & 15, ty = tid >> 4;
    int n0 = blockIdx.x * 64, d0 = blockIdx.y * 64;
    float acc[4][4] = {};
    for (int h0 = 0; h0 < HH; h0 += 16) {
#pragma unroll
        for (int i = 0; i < 4; ++i) {
            int idx = tid + i * 256;
            int k = idx & 15, n = idx >> 4;
            int gn = n0 + n;
            As[k][n] = (gn < NN) ? A[(size_t)gn * HH + h0 + k] : 0.f;
            Ws[k][n] = W[(size_t)(d0 + n) * HH + h0 + k];
        }
        __syncthreads();
#pragma unroll
        for (int k = 0; k < 16; ++k) {
            float a[4], b[4];
#pragma unroll
            for (int i = 0; i < 4; ++i) a[i] = As[k][ty + 16 * i];
#pragma unroll
            for (int j = 0; j < 4; ++j) b[j] = Ws[k][tx + 16 * j];
#pragma unroll
            for (int i = 0; i < 4; ++i)
#pragma unroll
                for (int j = 0; j < 4; ++j)
                    acc[i][j] = fmaf(a[i], b[j], acc[i][j]);
        }
        __syncthreads();
    }
#pragma unroll
    for (int i = 0; i < 4; ++i) {
        int n = n0 + ty + 16 * i;
        if (n >= NN) continue;
#pragma unroll
        for (int j = 0; j < 4; ++j) {
            float v = acc[i][j];
            if (doElu) v = elu1(v);
            P[(size_t)n * (4 * DD) + slot * DD + d0 + tx + 16 * j] = __float2half(v);
        }
    }
}

// ---------------------------------------------------------------------------
// Kernel 4: per-node sums. One warp per node.
// ---------------------------------------------------------------------------
__global__ void nodestat_kernel(const __half* __restrict__ P, float* __restrict__ NS) {
    int gw   = (blockIdx.x * blockDim.x + threadIdx.x) >> 5;
    int lane = threadIdx.x & 31;
    if (gw >= NN) return;
    const float4* p = reinterpret_cast<const float4*>(P) + ((size_t)gw << 7);
    float s[4];
#pragma unroll
    for (int k = 0; k < 4; ++k) {
        float f[8];
        cvt8(p[k * 32 + lane], f);
        float ss = 0.f;
#pragma unroll
        for (int j = 0; j < 8; ++j) ss += f[j];
        s[k] = ss;
    }
#pragma unroll
    for (int o = 16; o; o >>= 1) {
#pragma unroll
        for (int k = 0; k < 4; ++k)
            s[k] += __shfl_xor_sync(0xffffffffu, s[k], o);
    }
    if (lane == 0) {
#pragma unroll
        for (int k = 0; k < 4; ++k) NS[gw * 8 + k] = s[k];
    }
}

// ---------------------------------------------------------------------------
// Kernel 5: per-relation weight sums. One warp per relation.
// ---------------------------------------------------------------------------
__global__ void relstat_kernel(const __half* __restrict__ wAB, float* __restrict__ RS) {
    int gw   = (blockIdx.x * blockDim.x + threadIdx.x) >> 5;
    int lane = threadIdx.x & 31;
    if (gw >= RR) return;
    const float4* p = reinterpret_cast<const float4*>(wAB) + ((size_t)gw << 6);
    float fa[8], fb[8];
    cvt8(p[lane], fa);
    cvt8(p[32 + lane], fb);
    float sA = 0.f, sB = 0.f;
#pragma unroll
    for (int j = 0; j < 8; ++j) {
        sA += fa[j];
        sB += fb[j];
    }
#pragma unroll
    for (int o = 16; o; o >>= 1) {
        sA += __shfl_xor_sync(0xffffffffu, sA, o);
        sB += __shfl_xor_sync(0xffffffffu, sB, o);
    }
    if (lane == 0) {
        RS[gw * 2]     = sA;
        RS[gw * 2 + 1] = sB;
    }
}

// ---------------------------------------------------------------------------
// Sort kernels: counting sort of edges by idx1 (2000 bins)
// ---------------------------------------------------------------------------
__global__ void hist_kernel(const int* __restrict__ idx1, int* __restrict__ cnt, int E) {
    int e = blockIdx.x * blockDim.x + threadIdx.x;
    if (e < E) atomicAdd(&cnt[idx1[e]], 1);
}

__global__ void __launch_bounds__(1024)
scan_kernel(const int* __restrict__ cnt, int* __restrict__ cur) {
    __shared__ int sp[1024];
    int t = threadIdx.x;
    int a = (2 * t < NN)     ? cnt[2 * t]     : 0;
    int b = (2 * t + 1 < NN) ? cnt[2 * t + 1] : 0;
    int sum = a + b;
    sp[t] = sum;
    __syncthreads();
    for (int s = 1; s < 1024; s <<= 1) {
        int v = (t >= s) ? sp[t - s] : 0;
        __syncthreads();
        sp[t] += v;
        __syncthreads();
    }
    int excl = sp[t] - sum;
    if (2 * t < NN)     cur[2 * t]     = excl;
    if (2 * t + 1 < NN) cur[2 * t + 1] = excl + a;
}

__global__ void scatter_kernel(const int* __restrict__ idx1, int* __restrict__ cur,
                               int* __restrict__ perm, int E) {
    int e = blockIdx.x * blockDim.x + threadIdx.x;
    if (e < E) {
        int pos = atomicAdd(&cur[idx1[e]], 1);
        perm[pos] = e;
    }
}

// ---------------------------------------------------------------------------
// Kernel 6: edge phase. TWO edges per warp, 16-lane segments, idx1-sorted
// processing order via perm (consecutive segments share the p1 node -> L1 hits).
// ---------------------------------------------------------------------------
__global__ void __launch_bounds__(256, 3)
edge_kernel(const __half* __restrict__ Ph, const __half* __restrict__ wABh,
            const float* __restrict__ NS, const float* __restrict__ RS,
            const int* __restrict__ idx1, const int* __restrict__ idx2,
            const int* __restrict__ idx3, const int* __restrict__ perm,
            float* __restrict__ out, int E) {
    int warp = (blockIdx.x * blockDim.x + threadIdx.x) >> 5;
    int lane = threadIdx.x & 31;
    int seg  = lane >> 4;
    int sl   = lane & 15;
    int e = warp * 2 + seg;
    bool live = (e < E);
    int ep = perm[live ? e : (E - 1)];   // actual edge id (sorted by idx1)

    int i1 = idx1[ep], i2 = idx2[ep], rr = idx3[ep];
    const float4* p1 = reinterpret_cast<const float4*>(Ph) + ((size_t)i1 << 7);
    const float4* p2 = reinterpret_cast<const float4*>(Ph) + ((size_t)i2 << 7);
    const float4* wp = reinterpret_cast<const float4*>(wABh) + ((size_t)rr << 6);

    float4 S1 = *reinterpret_cast<const float4*>(NS + i1 * 8);
    float4 S2 = *reinterpret_cast<const float4*>(NS + i2 * 8);

    // Wave 1: R1 = x1[i1]+xfp[i2], I1 = x2[i1]+xskip[i2]
    __half2 R1h[8], I1h[8], R2h[8], I2h[8];
    float qR1 = 0.f, qI1 = 0.f, qR2 = 0.f, qI2 = 0.f;
    {
        float4 a0l = p1[sl],        a0h = p1[16 + sl];
        float4 b2l = p2[64 + sl],   b2h = p2[80 + sl];
        float4 a1l = p1[32 + sl],   a1h = p1[48 + sl];
        float4 b3l = p2[96 + sl],   b3h = p2[112 + sl];
        comb4(a0l, b2l, R1h,     qR1);
        comb4(a0h, b2h, R1h + 4, qR1);
        comb4(a1l, b3l, I1h,     qI1);
        comb4(a1h, b3h, I1h + 4, qI1);
    }
    // Wave 2: R2 = xskip[i1]+x2[i2], I2 = xfp[i1]+x1[i2]
    {
        float4 a3l = p1[96 + sl],   a3h = p1[112 + sl];
        float4 b1l = p2[32 + sl],   b1h = p2[48 + sl];
        float4 a2l = p1[64 + sl],   a2h = p1[80 + sl];
        float4 b0l = p2[sl],        b0h = p2[16 + sl];
        comb4(a3l, b1l, R2h,     qR2);
        comb4(a3h, b1h, R2h + 4, qR2);
        comb4(a2l, b0l, I2h,     qI2);
        comb4(a2h, b0h, I2h + 4, qI2);
    }

    float4 rwal = wp[sl],      rwah = wp[16 + sl];
    float4 rwbl = wp[32 + sl], rwbh = wp[48 + sl];

    // Tree A: 4 sumsq values, 4-stage segment butterfly
#pragma unroll
    for (int o = 8; o; o >>= 1) {
        qR1 += __shfl_xor_sync(0xffffffffu, qR1, o);
        qI1 += __shfl_xor_sync(0xffffffffu, qI1, o);
        qR2 += __shfl_xor_sync(0xffffffffu, qR2, o);
        qI2 += __shfl_xor_sync(0xffffffffu, qI2, o);
    }

    const float rD = 1.f / DD;
    float mR1 = (S1.x + S2.z) * rD;
    float mI1 = (S1.y + S2.w) * rD;
    float mR2 = (S1.w + S2.y) * rD;
    float mI2 = (S1.z + S2.x) * rD;
    float vR1 = rsqrtf(fmaf(-mR1, mR1, qR1 * rD) + 1e-5f);
    float vI1 = rsqrtf(fmaf(-mI1, mI1, qI1 * rD) + 1e-5f);
    float vR2 = rsqrtf(fmaf(-mR2, mR2, qR2 * rD) + 1e-5f);
    float vI2 = rsqrtf(fmaf(-mI2, mI2, qI2 * rD) + 1e-5f);
    float nR1 = -mR1 * vR1, nI1 = -mI1 * vI1, nR2 = -mR2 * vR2, nI2 = -mI2 * vI2;

    float s2A = 0.f, s2B = 0.f, q2A = 0.f, q2B = 0.f, dA = 0.f, dB = 0.f;
#pragma unroll
    for (int v = 0; v < 8; ++v) {
        float2 f1 = __half22float2(R1h[v]);
        float2 g1 = __half22float2(I1h[v]);
        float2 f2 = __half22float2(R2h[v]);
        float2 g2 = __half22float2(I2h[v]);
        float2 fa = __half22float2((v < 4) ? h2(rwal, v) : h2(rwah, v - 4));
        float2 fb = __half22float2((v < 4) ? h2(rwbl, v) : h2(rwbh, v - 4));
#pragma unroll
        for (int c = 0; c < 2; ++c) {
            float x1v = c ? f1.y : f1.x;
            float y1v = c ? g1.y : g1.x;
            float x2v = c ? f2.y : f2.x;
            float y2v = c ? g2.y : g2.x;
            float wav = c ? fa.y : fa.x;
            float wbv = c ? fb.y : fb.x;
            float r1  = fmaf(x1v, vR1, nR1);
            float i1v = fmaf(y1v, vI1, nI1);
            float r2  = fmaf(x2v, vR2, nR2);
            float i2v = fmaf(y2v, vI2, nI2);
            float rc = fmaf(r1, r2, -i1v * i2v);
            float ic = fmaf(r1, i2v, i1v * r2);
            s2A += rc;
            s2B += ic;
            q2A = fmaf(rc, rc, q2A);
            q2B = fmaf(ic, ic, q2B);
            dA = fmaf(rc, wav, dA);
            dB = fmaf(ic, wbv, dB);
        }
    }

    // Tree B: 6 values, 4-stage segment butterfly
#pragma unroll
    for (int o = 8; o; o >>= 1) {
        s2A += __shfl_xor_sync(0xffffffffu, s2A, o);
        s2B += __shfl_xor_sync(0xffffffffu, s2B, o);
        q2A += __shfl_xor_sync(0xffffffffu, q2A, o);
        q2B += __shfl_xor_sync(0xffffffffu, q2B, o);
        dA  += __shfl_xor_sync(0xffffffffu, dA, o);
        dB  += __shfl_xor_sync(0xffffffffu, dB, o);
    }

    if (sl == 0 && live) {
        float sAr = RS[rr * 2], sBr = RS[rr * 2 + 1];
        float mA = s2A * rD;
        float mB = s2B * rD;
        float invA = rsqrtf(fmaf(-mA, mA, q2A * rD) + 1e-5f);
        float invB = rsqrtf(fmaf(-mB, mB, q2B * rD) + 1e-5f);
        float acc = invA * fmaf(-mA, sAr, dA) + invB * fmaf(-mB, sBr, dB);
        out[ep] = 1.f / (1.f + expf(-acc));
    }
}

// ---------------------------------------------------------------------------
extern "C" void kernel_launch(void* const* d_in, const int* in_sizes, int n_in,
                              void* d_out, int out_size) {
    const float* drug_fp   = (const float*)d_in[0];
    const float* drug_init = (const float*)d_in[1];
    const float* x1        = (const float*)d_in[2];
    const float* x2        = (const float*)d_in[3];
    const float* W_fp      = (const float*)d_in[4];
    const float* W_skip    = (const float*)d_in[5];
    const float* wr        = (const float*)d_in[6];
    const float* wi        = (const float*)d_in[7];
    const int*   idx1      = (const int*)d_in[8];
    const int*   idx2      = (const int*)d_in[9];
    const int*   idx3      = (const int*)d_in[10];
    float*       out       = (float*)d_out;
    int E = in_sizes[8];

    float *fpn, *NS, *RS;
    __half *P, *wAB;
    int *cnt, *cur, *perm;
    cudaGetSymbolAddress((void**)&fpn,  g_fpn);
    cudaGetSymbolAddress((void**)&P,    g_P);
    cudaGetSymbolAddress((void**)&wAB,  g_wAB);
    cudaGetSymbolAddress((void**)&NS,   g_NS);
    cudaGetSymbolAddress((void**)&RS,   g_RS);
    cudaGetSymbolAddress((void**)&cnt,  g_cnt);
    cudaGetSymbolAddress((void**)&cur,  g_cur);
    cudaGetSymbolAddress((void**)&perm, g_perm);

    // Sort edges by idx1 (runs first; independent of the value pipeline)
    cudaMemsetAsync(cnt, 0, NN * sizeof(int));
    hist_kernel<<<(E + 255) / 256, 256>>>(idx1, cnt, E);
    scan_kernel<<<1, 1024>>>(cnt, cur);
    scatter_kernel<<<(E + 255) / 256, 256>>>(idx1, cur, perm, E);

    // 1) fp_n = elu(LN(drug_fp))
    lnelu512_kernel<<<(NN * 32 + 255) / 256, 256>>>(drug_fp, fpn);

    // 2) pack x1/x2 and relation weights (fp16)
    pack_kernel<<<(NN * DD + 255) / 256, 256>>>(x1, x2, wr, wi, P, wAB);

    // 3) GEMMs -> slots 2/3 of P (fp16)
    dim3 gg((NN + 63) / 64, DD / 64, 2);
    gemm_nt_kernel<<<gg, 256>>>(fpn, W_fp, drug_init, W_skip, P);

    // 4) per-node and per-relation sums
    nodestat_kernel<<<(NN * 32 + 255) / 256, 256>>>(P, NS);
    relstat_kernel<<<(RR * 32 + 255) / 256, 256>>>(wAB, RS);

    // 5) edge phase: two edges per warp, sorted order
    edge_kernel<<<(E + 15) / 16, 256>>>(P, wAB, NS, RS, idx1, idx2, idx3, perm, out, E);
}

// round 13
// speedup vs baseline: 1.0933x; 1.0933x over previous
#include <cuda_runtime.h>
#include <cuda_fp16.h>
#include <math.h>

#define NN 2000   // nodes
#define HH 512    // hidden
#define DD 256    // embed dim
#define RR 86     // relations

// Scratch
__device__ float  g_fpn[NN * HH];
__device__ __half g_P[NN * 4 * DD];     // per node: [x1 | x2 | xfp | xskip] (fp16)
__device__ __half g_wAB[RR * 2 * DD];   // per relation: [wr-wi | wr+wi] (fp16)
__device__ float  g_NS[NN * 8];         // per node: S[4]
__device__ float  g_RS[RR * 2];         // per relation: sum(wA), sum(wB)

__device__ __forceinline__ float elu1(float x) {
    return x > 0.f ? x : expm1f(x);
}
__device__ __forceinline__ float sum4(const float4& v) {
    return (v.x + v.y) + (v.z + v.w);
}
__device__ __forceinline__ float sq4(const float4& v) {
    float q = v.x * v.x;
    q = fmaf(v.y, v.y, q);
    q = fmaf(v.z, v.z, q);
    q = fmaf(v.w, v.w, q);
    return q;
}
__device__ __forceinline__ void cvt8(const float4& r, float* f) {
    const __half2* h = reinterpret_cast<const __half2*>(&r);
#pragma unroll
    for (int i = 0; i < 4; ++i) {
        float2 t = __half22float2(h[i]);
        f[2 * i]     = t.x;
        f[2 * i + 1] = t.y;
    }
}
__device__ __forceinline__ __half2 h2(const float4& r, int k) {
    return reinterpret_cast<const __half2*>(&r)[k];
}
__device__ __forceinline__ void comb4(const float4& ra, const float4& rb,
                                      __half2* o, float& q) {
#pragma unroll
    for (int k = 0; k < 4; ++k) {
        __half2 s = __hadd2(h2(ra, k), h2(rb, k));
        o[k] = s;
        float2 t = __half22float2(s);
        q = fmaf(t.x, t.x, q);
        q = fmaf(t.y, t.y, q);
    }
}

// ---------------------------------------------------------------------------
// Kernel 1: fp_n = elu(LayerNorm(drug_fp)), one warp per row (H=512)
// ---------------------------------------------------------------------------
__global__ void lnelu512_kernel(const float* __restrict__ in, float* __restrict__ out) {
    int gw   = (blockIdx.x * blockDim.x + threadIdx.x) >> 5;
    int lane = threadIdx.x & 31;
    if (gw >= NN) return;
    const float4* p = reinterpret_cast<const float4*>(in + (size_t)gw * HH);
    float4 v[4];
    float s = 0.f, q = 0.f;
#pragma unroll
    for (int i = 0; i < 4; ++i) {
        v[i] = p[lane + 32 * i];
        s += sum4(v[i]);
        q += sq4(v[i]);
    }
#pragma unroll
    for (int o = 16; o; o >>= 1) {
        s += __shfl_xor_sync(0xffffffffu, s, o);
        q += __shfl_xor_sync(0xffffffffu, q, o);
    }
    float m   = s * (1.f / HH);
    float var = fmaf(-m, m, q * (1.f / HH));
    float inv = rsqrtf(var + 1e-5f);
    float4* o4 = reinterpret_cast<float4*>(out + (size_t)gw * HH);
#pragma unroll
    for (int i = 0; i < 4; ++i) {
        float4 y;
        y.x = elu1((v[i].x - m) * inv);
        y.y = elu1((v[i].y - m) * inv);
        y.z = elu1((v[i].z - m) * inv);
        y.w = elu1((v[i].w - m) * inv);
        o4[lane + 32 * i] = y;
    }
}

// ---------------------------------------------------------------------------
// Kernel 2: pack x1/x2 into P (fp16), precombine relation weights (fp16)
// ---------------------------------------------------------------------------
__global__ void pack_kernel(const float* __restrict__ x1, const float* __restrict__ x2,
                            const float* __restrict__ wr, const float* __restrict__ wi,
                            __half* __restrict__ P, __half* __restrict__ wAB) {
    int i = blockIdx.x * blockDim.x + threadIdx.x;
    if (i < NN * DD) {
        int n = i >> 8, d = i & 255;
        P[(size_t)n * (4 * DD) + d]      = __float2half(x1[i]);
        P[(size_t)n * (4 * DD) + DD + d] = __float2half(x2[i]);
    }
    if (i < RR * DD) {
        int r = i >> 8, d = i & 255;
        float a = wr[i], b = wi[i];
        wAB[(size_t)r * (2 * DD) + d]      = __float2half(a - b);
        wAB[(size_t)r * (2 * DD) + DD + d] = __float2half(a + b);
    }
}

// ---------------------------------------------------------------------------
// Kernel 3: GEMM C[n,slot,d] = (elu?)(sum_h A[n,h] * W[d,h]) -> fp16 into P
// ---------------------------------------------------------------------------
__global__ void __launch_bounds__(256)
gemm_nt_kernel(const float* __restrict__ A0, const float* __restrict__ W0,
               const float* __restrict__ A1, const float* __restrict__ W1,
               __half* __restrict__ P) {
    __shared__ float As[16][65];
    __shared__ float Ws[16][65];
    const float* A = blockIdx.z ? A1 : A0;
    const float* W = blockIdx.z ? W1 : W0;
    int slot = blockIdx.z ? 3 : 2;
    int doElu = blockIdx.z ? 0 : 1;
    int tid = threadIdx.x;
    int tx = tid & 15, ty = tid >> 4;
    int n0 = blockIdx.x * 64, d0 = blockIdx.y * 64;
    float acc[4][4] = {};
    for (int h0 = 0; h0 < HH; h0 += 16) {
#pragma unroll
        for (int i = 0; i < 4; ++i) {
            int idx = tid + i * 256;
            int k = idx & 15, n = idx >> 4;
            int gn = n0 + n;
            As[k][n] = (gn < NN) ? A[(size_t)gn * HH + h0 + k] : 0.f;
            Ws[k][n] = W[(size_t)(d0 + n) * HH + h0 + k];
        }
        __syncthreads();
#pragma unroll
        for (int k = 0; k < 16; ++k) {
            float a[4], b[4];
#pragma unroll
            for (int i = 0; i < 4; ++i) a[i] = As[k][ty + 16 * i];
#pragma unroll
            for (int j = 0; j < 4; ++j) b[j] = Ws[k][tx + 16 * j];
#pragma unroll
            for (int i = 0; i < 4; ++i)
#pragma unroll
                for (int j = 0; j < 4; ++j)
                    acc[i][j] = fmaf(a[i], b[j], acc[i][j]);
        }
        __syncthreads();
    }
#pragma unroll
    for (int i = 0; i < 4; ++i) {
        int n = n0 + ty + 16 * i;
        if (n >= NN) continue;
#pragma unroll
        for (int j = 0; j < 4; ++j) {
            float v = acc[i][j];
            if (doElu) v = elu1(v);
            P[(size_t)n * (4 * DD) + slot * DD + d0 + tx + 16 * j] = __float2half(v);
        }
    }
}

// ---------------------------------------------------------------------------
// Kernel 4: per-node sums. One warp per node.
// ---------------------------------------------------------------------------
__global__ void nodestat_kernel(const __half* __restrict__ P, float* __restrict__ NS) {
    int gw   = (blockIdx.x * blockDim.x + threadIdx.x) >> 5;
    int lane = threadIdx.x & 31;
    if (gw >= NN) return;
    const float4* p = reinterpret_cast<const float4*>(P) + ((size_t)gw << 7);
    float s[4];
#pragma unroll
    for (int k = 0; k < 4; ++k) {
        float f[8];
        cvt8(p[k * 32 + lane], f);
        float ss = 0.f;
#pragma unroll
        for (int j = 0; j < 8; ++j) ss += f[j];
        s[k] = ss;
    }
#pragma unroll
    for (int o = 16; o; o >>= 1) {
#pragma unroll
        for (int k = 0; k < 4; ++k)
            s[k] += __shfl_xor_sync(0xffffffffu, s[k], o);
    }
    if (lane == 0) {
#pragma unroll
        for (int k = 0; k < 4; ++k) NS[gw * 8 + k] = s[k];
    }
}

// ---------------------------------------------------------------------------
// Kernel 5: per-relation weight sums. One warp per relation.
// ---------------------------------------------------------------------------
__global__ void relstat_kernel(const __half* __restrict__ wAB, float* __restrict__ RS) {
    int gw   = (blockIdx.x * blockDim.x + threadIdx.x) >> 5;
    int lane = threadIdx.x & 31;
    if (gw >= RR) return;
    const float4* p = reinterpret_cast<const float4*>(wAB) + ((size_t)gw << 6);
    float fa[8], fb[8];
    cvt8(p[lane], fa);
    cvt8(p[32 + lane], fb);
    float sA = 0.f, sB = 0.f;
#pragma unroll
    for (int j = 0; j < 8; ++j) {
        sA += fa[j];
        sB += fb[j];
    }
#pragma unroll
    for (int o = 16; o; o >>= 1) {
        sA += __shfl_xor_sync(0xffffffffu, sA, o);
        sB += __shfl_xor_sync(0xffffffffu, sB, o);
    }
    if (lane == 0) {
        RS[gw * 2]     = sA;
        RS[gw * 2 + 1] = sB;
    }
}

// ---------------------------------------------------------------------------
// Kernel 6: edge phase. TWO edges per warp, 16-lane segments.
// NS / weight loads deferred past tree A to shorten live ranges; 64-reg cap
// for 4 CTAs/SM (32 warps).
// ---------------------------------------------------------------------------
__global__ void __launch_bounds__(256, 4)
edge_kernel(const __half* __restrict__ Ph, const __half* __restrict__ wABh,
            const float* __restrict__ NS, const float* __restrict__ RS,
            const int* __restrict__ idx1, const int* __restrict__ idx2,
            const int* __restrict__ idx3,
            float* __restrict__ out, int E) {
    int warp = (blockIdx.x * blockDim.x + threadIdx.x) >> 5;
    int lane = threadIdx.x & 31;
    int seg  = lane >> 4;
    int sl   = lane & 15;
    int e = warp * 2 + seg;
    bool live = (e < E);
    int ec = live ? e : (E - 1);

    int i1 = idx1[ec], i2 = idx2[ec], rr = idx3[ec];
    const float4* p1 = reinterpret_cast<const float4*>(Ph) + ((size_t)i1 << 7);
    const float4* p2 = reinterpret_cast<const float4*>(Ph) + ((size_t)i2 << 7);

    // Wave 1: R1 = x1[i1]+xfp[i2], I1 = x2[i1]+xskip[i2]
    __half2 R1h[8], I1h[8], R2h[8], I2h[8];
    float qR1 = 0.f, qI1 = 0.f, qR2 = 0.f, qI2 = 0.f;
    {
        float4 a0l = p1[sl],        a0h = p1[16 + sl];
        float4 b2l = p2[64 + sl],   b2h = p2[80 + sl];
        float4 a1l = p1[32 + sl],   a1h = p1[48 + sl];
        float4 b3l = p2[96 + sl],   b3h = p2[112 + sl];
        comb4(a0l, b2l, R1h,     qR1);
        comb4(a0h, b2h, R1h + 4, qR1);
        comb4(a1l, b3l, I1h,     qI1);
        comb4(a1h, b3h, I1h + 4, qI1);
    }
    // Wave 2: R2 = xskip[i1]+x2[i2], I2 = xfp[i1]+x1[i2]
    {
        float4 a3l = p1[96 + sl],   a3h = p1[112 + sl];
        float4 b1l = p2[32 + sl],   b1h = p2[48 + sl];
        float4 a2l = p1[64 + sl],   a2h = p1[80 + sl];
        float4 b0l = p2[sl],        b0h = p2[16 + sl];
        comb4(a3l, b1l, R2h,     qR2);
        comb4(a3h, b1h, R2h + 4, qR2);
        comb4(a2l, b0l, I2h,     qI2);
        comb4(a2h, b0h, I2h + 4, qI2);
    }

    // Tree A: 4 sumsq values, 4-stage segment butterfly
#pragma unroll
    for (int o = 8; o; o >>= 1) {
        qR1 += __shfl_xor_sync(0xffffffffu, qR1, o);
        qI1 += __shfl_xor_sync(0xffffffffu, qI1, o);
        qR2 += __shfl_xor_sync(0xffffffffu, qR2, o);
        qI2 += __shfl_xor_sync(0xffffffffu, qI2, o);
    }

    // Node sums loaded AFTER tree A (L1-resident broadcast; short live range)
    float4 S1 = *reinterpret_cast<const float4*>(NS + i1 * 8);
    float4 S2 = *reinterpret_cast<const float4*>(NS + i2 * 8);

    const float rD = 1.f / DD;
    float mR1 = (S1.x + S2.z) * rD;
    float mI1 = (S1.y + S2.w) * rD;
    float mR2 = (S1.w + S2.y) * rD;
    float mI2 = (S1.z + S2.x) * rD;
    float vR1 = rsqrtf(fmaf(-mR1, mR1, qR1 * rD) + 1e-5f);
    float vI1 = rsqrtf(fmaf(-mI1, mI1, qI1 * rD) + 1e-5f);
    float vR2 = rsqrtf(fmaf(-mR2, mR2, qR2 * rD) + 1e-5f);
    float vI2 = rsqrtf(fmaf(-mI2, mI2, qI2 * rD) + 1e-5f);
    float nR1 = -mR1 * vR1, nI1 = -mI1 * vI1, nR2 = -mR2 * vR2, nI2 = -mI2 * vI2;

    // Weight rows loaded here (L1-resident, 88 KB table); consumed immediately
    const float4* wp = reinterpret_cast<const float4*>(wABh) + ((size_t)rr << 6);
    float4 rwal = wp[sl],      rwah = wp[16 + sl];
    float4 rwbl = wp[32 + sl], rwbh = wp[48 + sl];

    float s2A = 0.f, s2B = 0.f, q2A = 0.f, q2B = 0.f, dA = 0.f, dB = 0.f;
#pragma unroll
    for (int v = 0; v < 8; ++v) {
        float2 f1 = __half22float2(R1h[v]);
        float2 g1 = __half22float2(I1h[v]);
        float2 f2 = __half22float2(R2h[v]);
        float2 g2 = __half22float2(I2h[v]);
        float2 fa = __half22float2((v < 4) ? h2(rwal, v) : h2(rwah, v - 4));
        float2 fb = __half22float2((v < 4) ? h2(rwbl, v) : h2(rwbh, v - 4));
#pragma unroll
        for (int c = 0; c < 2; ++c) {
            float x1v = c ? f1.y : f1.x;
            float y1v = c ? g1.y : g1.x;
            float x2v = c ? f2.y : f2.x;
            float y2v = c ? g2.y : g2.x;
            float wav = c ? fa.y : fa.x;
            float wbv = c ? fb.y : fb.x;
            float r1  = fmaf(x1v, vR1, nR1);
            float i1v = fmaf(y1v, vI1, nI1);
            float r2  = fmaf(x2v, vR2, nR2);
            float i2v = fmaf(y2v, vI2, nI2);
            float rc = fmaf(r1, r2, -i1v * i2v);
            float ic = fmaf(r1, i2v, i1v * r2);
            s2A += rc;
            s2B += ic;
            q2A = fmaf(rc, rc, q2A);
            q2B = fmaf(ic, ic, q2B);
            dA = fmaf(rc, wav, dA);
            dB = fmaf(ic, wbv, dB);
        }
    }

    // Tree B: 6 values, 4-stage segment butterfly
#pragma unroll
    for (int o = 8; o; o >>= 1) {
        s2A += __shfl_xor_sync(0xffffffffu, s2A, o);
        s2B += __shfl_xor_sync(0xffffffffu, s2B, o);
        q2A += __shfl_xor_sync(0xffffffffu, q2A, o);
        q2B += __shfl_xor_sync(0xffffffffu, q2B, o);
        dA  += __shfl_xor_sync(0xffffffffu, dA, o);
        dB  += __shfl_xor_sync(0xffffffffu, dB, o);
    }

    if (sl == 0 && live) {
        float sAr = RS[rr * 2], sBr = RS[rr * 2 + 1];
        float mA = s2A * rD;
        float mB = s2B * rD;
        float invA = rsqrtf(fmaf(-mA, mA, q2A * rD) + 1e-5f);
        float invB = rsqrtf(fmaf(-mB, mB, q2B * rD) + 1e-5f);
        float acc = invA * fmaf(-mA, sAr, dA) + invB * fmaf(-mB, sBr, dB);
        out[e] = 1.f / (1.f + expf(-acc));
    }
}

// ---------------------------------------------------------------------------
extern "C" void kernel_launch(void* const* d_in, const int* in_sizes, int n_in,
                              void* d_out, int out_size) {
    const float* drug_fp   = (const float*)d_in[0];
    const float* drug_init = (const float*)d_in[1];
    const float* x1        = (const float*)d_in[2];
    const float* x2        = (const float*)d_in[3];
    const float* W_fp      = (const float*)d_in[4];
    const float* W_skip    = (const float*)d_in[5];
    const float* wr        = (const float*)d_in[6];
    const float* wi        = (const float*)d_in[7];
    const int*   idx1      = (const int*)d_in[8];
    const int*   idx2      = (const int*)d_in[9];
    const int*   idx3      = (const int*)d_in[10];
    float*       out       = (float*)d_out;
    int E = in_sizes[8];

    float *fpn, *NS, *RS;
    __half *P, *wAB;
    cudaGetSymbolAddress((void**)&fpn, g_fpn);
    cudaGetSymbolAddress((void**)&P,   g_P);
    cudaGetSymbolAddress((void**)&wAB, g_wAB);
    cudaGetSymbolAddress((void**)&NS,  g_NS);
    cudaGetSymbolAddress((void**)&RS,  g_RS);

    // 1) fp_n = elu(LN(drug_fp))
    lnelu512_kernel<<<(NN * 32 + 255) / 256, 256>>>(drug_fp, fpn);

    // 2) pack x1/x2 and relation weights (fp16)
    pack_kernel<<<(NN * DD + 255) / 256, 256>>>(x1, x2, wr, wi, P, wAB);

    // 3) GEMMs -> slots 2/3 of P (fp16)
    dim3 gg((NN + 63) / 64, DD / 64, 2);
    gemm_nt_kernel<<<gg, 256>>>(fpn, W_fp, drug_init, W_skip, P);

    // 4) per-node and per-relation sums
    nodestat_kernel<<<(NN * 32 + 255) / 256, 256>>>(P, NS);
    relstat_kernel<<<(RR * 32 + 255) / 256, 256>>>(wAB, RS);

    // 5) edge phase: two edges per warp
    edge_kernel<<<(E + 15) / 16, 256>>>(P, wAB, NS, RS, idx1, idx2, idx3, out, E);
}

// round 16
// speedup vs baseline: 1.2165x; 1.1127x over previous
#include <cuda_runtime.h>
#include <cuda_fp16.h>
#include <math.h>

#define NN 2000   // nodes
#define HH 512    // hidden
#define DD 256    // embed dim
#define RR 86     // relations

// Scratch
__device__ float  g_fpn[NN * HH];
__device__ __half g_P[NN * 4 * DD];     // per node: [x1 | x2 | xfp | xskip] (fp16)
__device__ __half g_wAB[RR * 2 * DD];   // per relation: [wr-wi | wr+wi] (fp16)
__device__ float  g_NS[NN * 8];         // per node: S[4]
__device__ float  g_RS[RR * 2];         // per relation: sum(wA), sum(wB)

__device__ __forceinline__ float elu1(float x) {
    return x > 0.f ? x : expm1f(x);
}
__device__ __forceinline__ float sum4(const float4& v) {
    return (v.x + v.y) + (v.z + v.w);
}
__device__ __forceinline__ float sq4(const float4& v) {
    float q = v.x * v.x;
    q = fmaf(v.y, v.y, q);
    q = fmaf(v.z, v.z, q);
    q = fmaf(v.w, v.w, q);
    return q;
}
__device__ __forceinline__ void cvt8(const float4& r, float* f) {
    const __half2* h = reinterpret_cast<const __half2*>(&r);
#pragma unroll
    for (int i = 0; i < 4; ++i) {
        float2 t = __half22float2(h[i]);
        f[2 * i]     = t.x;
        f[2 * i + 1] = t.y;
    }
}
__device__ __forceinline__ __half2 h2(const float4& r, int k) {
    return reinterpret_cast<const __half2*>(&r)[k];
}
__device__ __forceinline__ void comb4(const float4& ra, const float4& rb,
                                      __half2* o, float& q) {
#pragma unroll
    for (int k = 0; k < 4; ++k) {
        __half2 s = __hadd2(h2(ra, k), h2(rb, k));
        o[k] = s;
        float2 t = __half22float2(s);
        q = fmaf(t.x, t.x, q);
        q = fmaf(t.y, t.y, q);
    }
}

// ---------------------------------------------------------------------------
// Kernel 1: fp_n = elu(LayerNorm(drug_fp)), one warp per row (H=512)
// ---------------------------------------------------------------------------
__global__ void lnelu512_kernel(const float* __restrict__ in, float* __restrict__ out) {
    int gw   = (blockIdx.x * blockDim.x + threadIdx.x) >> 5;
    int lane = threadIdx.x & 31;
    if (gw >= NN) return;
    const float4* p = reinterpret_cast<const float4*>(in + (size_t)gw * HH);
    float4 v[4];
    float s = 0.f, q = 0.f;
#pragma unroll
    for (int i = 0; i < 4; ++i) {
        v[i] = p[lane + 32 * i];
        s += sum4(v[i]);
        q += sq4(v[i]);
    }
#pragma unroll
    for (int o = 16; o; o >>= 1) {
        s += __shfl_xor_sync(0xffffffffu, s, o);
        q += __shfl_xor_sync(0xffffffffu, q, o);
    }
    float m   = s * (1.f / HH);
    float var = fmaf(-m, m, q * (1.f / HH));
    float inv = rsqrtf(var + 1e-5f);
    float4* o4 = reinterpret_cast<float4*>(out + (size_t)gw * HH);
#pragma unroll
    for (int i = 0; i < 4; ++i) {
        float4 y;
        y.x = elu1((v[i].x - m) * inv);
        y.y = elu1((v[i].y - m) * inv);
        y.z = elu1((v[i].z - m) * inv);
        y.w = elu1((v[i].w - m) * inv);
        o4[lane + 32 * i] = y;
    }
}

// ---------------------------------------------------------------------------
// Kernel 2: pack x1/x2 into P (fp16), precombine relation weights (fp16)
// ---------------------------------------------------------------------------
__global__ void pack_kernel(const float* __restrict__ x1, const float* __restrict__ x2,
                            const float* __restrict__ wr, const float* __restrict__ wi,
                            __half* __restrict__ P, __half* __restrict__ wAB) {
    int i = blockIdx.x * blockDim.x + threadIdx.x;
    if (i < NN * DD) {
        int n = i >> 8, d = i & 255;
        P[(size_t)n * (4 * DD) + d]      = __float2half(x1[i]);
        P[(size_t)n * (4 * DD) + DD + d] = __float2half(x2[i]);
    }
    if (i < RR * DD) {
        int r = i >> 8, d = i & 255;
        float a = wr[i], b = wi[i];
        wAB[(size_t)r * (2 * DD) + d]      = __float2half(a - b);
        wAB[(size_t)r * (2 * DD) + DD + d] = __float2half(a + b);
    }
}

// ---------------------------------------------------------------------------
// Kernel 3: GEMM C[n,slot,d] = (elu?)(sum_h A[n,h] * W[d,h]) -> fp16 into P
// ---------------------------------------------------------------------------
__global__ void __launch_bounds__(256)
gemm_nt_kernel(const float* __restrict__ A0, const float* __restrict__ W0,
               const float* __restrict__ A1, const float* __restrict__ W1,
               __half* __restrict__ P) {
    __shared__ float As[16][65];
    __shared__ float Ws[16][65];
    const float* A = blockIdx.z ? A1 : A0;
    const float* W = blockIdx.z ? W1 : W0;
    int slot = blockIdx.z ? 3 : 2;
    int doElu = blockIdx.z ? 0 : 1;
    int tid = threadIdx.x;
    int tx = tid & 15, ty = tid >> 4;
    int n0 = blockIdx.x * 64, d0 = blockIdx.y * 64;
    float acc[4][4] = {};
    for (int h0 = 0; h0 < HH; h0 += 16) {
#pragma unroll
        for (int i = 0; i < 4; ++i) {
            int idx = tid + i * 256;
            int k = idx & 15, n = idx >> 4;
            int gn = n0 + n;
            As[k][n] = (gn < NN) ? A[(size_t)gn * HH + h0 + k] : 0.f;
            Ws[k][n] = W[(size_t)(d0 + n) * HH + h0 + k];
        }
        __syncthreads();
#pragma unroll
        for (int k = 0; k < 16; ++k) {
            float a[4], b[4];
#pragma unroll
            for (int i = 0; i < 4; ++i) a[i] = As[k][ty + 16 * i];
#pragma unroll
            for (int j = 0; j < 4; ++j) b[j] = Ws[k][tx + 16 * j];
#pragma unroll
            for (int i = 0; i < 4; ++i)
#pragma unroll
                for (int j = 0; j < 4; ++j)
                    acc[i][j] = fmaf(a[i], b[j], acc[i][j]);
        }
        __syncthreads();
    }
#pragma unroll
    for (int i = 0; i < 4; ++i) {
        int n = n0 + ty + 16 * i;
        if (n >= NN) continue;
#pragma unroll
        for (int j = 0; j < 4; ++j) {
            float v = acc[i][j];
            if (doElu) v = elu1(v);
            P[(size_t)n * (4 * DD) + slot * DD + d0 + tx + 16 * j] = __float2half(v);
        }
    }
}

// ---------------------------------------------------------------------------
// Kernel 4: merged stats. Warps [0, NN) -> per-node sums; warps [NN, NN+RR)
// -> per-relation weight sums. One launch instead of two.
// ---------------------------------------------------------------------------
__global__ void stats_kernel(const __half* __restrict__ P, const __half* __restrict__ wAB,
                             float* __restrict__ NS, float* __restrict__ RS) {
    int gw   = (blockIdx.x * blockDim.x + threadIdx.x) >> 5;
    int lane = threadIdx.x & 31;
    if (gw < NN) {
        const float4* p = reinterpret_cast<const float4*>(P) + ((size_t)gw << 7);
        float s[4];
#pragma unroll
        for (int k = 0; k < 4; ++k) {
            float f[8];
            cvt8(p[k * 32 + lane], f);
            float ss = 0.f;
#pragma unroll
            for (int j = 0; j < 8; ++j) ss += f[j];
            s[k] = ss;
        }
#pragma unroll
        for (int o = 16; o; o >>= 1) {
#pragma unroll
            for (int k = 0; k < 4; ++k)
                s[k] += __shfl_xor_sync(0xffffffffu, s[k], o);
        }
        if (lane == 0) {
#pragma unroll
            for (int k = 0; k < 4; ++k) NS[gw * 8 + k] = s[k];
        }
    } else if (gw < NN + RR) {
        int r = gw - NN;
        const float4* p = reinterpret_cast<const float4*>(wAB) + ((size_t)r << 6);
        float fa[8], fb[8];
        cvt8(p[lane], fa);
        cvt8(p[32 + lane], fb);
        float sA = 0.f, sB = 0.f;
#pragma unroll
        for (int j = 0; j < 8; ++j) {
            sA += fa[j];
            sB += fb[j];
        }
#pragma unroll
        for (int o = 16; o; o >>= 1) {
            sA += __shfl_xor_sync(0xffffffffu, sA, o);
            sB += __shfl_xor_sync(0xffffffffu, sB, o);
        }
        if (lane == 0) {
            RS[r * 2]     = sA;
            RS[r * 2 + 1] = sB;
        }
    }
}

// ---------------------------------------------------------------------------
// Kernel 5: edge phase (R10 configuration — early loads, 3 CTAs/SM).
// TWO edges per warp, 16-lane segments; segment butterflies (offsets 8/4/2/1).
// ---------------------------------------------------------------------------
__global__ void __launch_bounds__(256, 3)
edge_kernel(const __half* __restrict__ Ph, const __half* __restrict__ wABh,
            const float* __restrict__ NS, const float* __restrict__ RS,
            const int* __restrict__ idx1, const int* __restrict__ idx2,
            const int* __restrict__ idx3,
            float* __restrict__ out, int E) {
    int warp = (blockIdx.x * blockDim.x + threadIdx.x) >> 5;
    int lane = threadIdx.x & 31;
    int seg  = lane >> 4;
    int sl   = lane & 15;
    int e = warp * 2 + seg;
    bool live = (e < E);
    int ec = live ? e : (E - 1);

    int i1 = idx1[ec], i2 = idx2[ec], rr = idx3[ec];
    const float4* p1 = reinterpret_cast<const float4*>(Ph) + ((size_t)i1 << 7);
    const float4* p2 = reinterpret_cast<const float4*>(Ph) + ((size_t)i2 << 7);
    const float4* wp = reinterpret_cast<const float4*>(wABh) + ((size_t)rr << 6);

    float4 S1 = *reinterpret_cast<const float4*>(NS + i1 * 8);
    float4 S2 = *reinterpret_cast<const float4*>(NS + i2 * 8);

    // Wave 1: R1 = x1[i1]+xfp[i2], I1 = x2[i1]+xskip[i2]
    __half2 R1h[8], I1h[8], R2h[8], I2h[8];
    float qR1 = 0.f, qI1 = 0.f, qR2 = 0.f, qI2 = 0.f;
    {
        float4 a0l = p1[sl],        a0h = p1[16 + sl];
        float4 b2l = p2[64 + sl],   b2h = p2[80 + sl];
        float4 a1l = p1[32 + sl],   a1h = p1[48 + sl];
        float4 b3l = p2[96 + sl],   b3h = p2[112 + sl];
        comb4(a0l, b2l, R1h,     qR1);
        comb4(a0h, b2h, R1h + 4, qR1);
        comb4(a1l, b3l, I1h,     qI1);
        comb4(a1h, b3h, I1h + 4, qI1);
    }
    // Wave 2: R2 = xskip[i1]+x2[i2], I2 = xfp[i1]+x1[i2]
    {
        float4 a3l = p1[96 + sl],   a3h = p1[112 + sl];
        float4 b1l = p2[32 + sl],   b1h = p2[48 + sl];
        float4 a2l = p1[64 + sl],   a2h = p1[80 + sl];
        float4 b0l = p2[sl],        b0h = p2[16 + sl];
        comb4(a3l, b1l, R2h,     qR2);
        comb4(a3h, b1h, R2h + 4, qR2);
        comb4(a2l, b0l, I2h,     qI2);
        comb4(a2h, b0h, I2h + 4, qI2);
    }

    float4 rwal = wp[sl],      rwah = wp[16 + sl];
    float4 rwbl = wp[32 + sl], rwbh = wp[48 + sl];

    // Tree A: 4 sumsq values, 4-stage segment butterfly
#pragma unroll
    for (int o = 8; o; o >>= 1) {
        qR1 += __shfl_xor_sync(0xffffffffu, qR1, o);
        qI1 += __shfl_xor_sync(0xffffffffu, qI1, o);
        qR2 += __shfl_xor_sync(0xffffffffu, qR2, o);
        qI2 += __shfl_xor_sync(0xffffffffu, qI2, o);
    }

    const float rD = 1.f / DD;
    float mR1 = (S1.x + S2.z) * rD;
    float mI1 = (S1.y + S2.w) * rD;
    float mR2 = (S1.w + S2.y) * rD;
    float mI2 = (S1.z + S2.x) * rD;
    float vR1 = rsqrtf(fmaf(-mR1, mR1, qR1 * rD) + 1e-5f);
    float vI1 = rsqrtf(fmaf(-mI1, mI1, qI1 * rD) + 1e-5f);
    float vR2 = rsqrtf(fmaf(-mR2, mR2, qR2 * rD) + 1e-5f);
    float vI2 = rsqrtf(fmaf(-mI2, mI2, qI2 * rD) + 1e-5f);
    float nR1 = -mR1 * vR1, nI1 = -mI1 * vI1, nR2 = -mR2 * vR2, nI2 = -mI2 * vI2;

    float s2A = 0.f, s2B = 0.f, q2A = 0.f, q2B = 0.f, dA = 0.f, dB = 0.f;
#pragma unroll
    for (int v = 0; v < 8; ++v) {
        float2 f1 = __half22float2(R1h[v]);
        float2 g1 = __half22float2(I1h[v]);
        float2 f2 = __half22float2(R2h[v]);
        float2 g2 = __half22float2(I2h[v]);
        float2 fa = __half22float2((v < 4) ? h2(rwal, v) : h2(rwah, v - 4));
        float2 fb = __half22float2((v < 4) ? h2(rwbl, v) : h2(rwbh, v - 4));
#pragma unroll
        for (int c = 0; c < 2; ++c) {
            float x1v = c ? f1.y : f1.x;
            float y1v = c ? g1.y : g1.x;
            float x2v = c ? f2.y : f2.x;
            float y2v = c ? g2.y : g2.x;
            float wav = c ? fa.y : fa.x;
            float wbv = c ? fb.y : fb.x;
            float r1  = fmaf(x1v, vR1, nR1);
            float i1v = fmaf(y1v, vI1, nI1);
            float r2  = fmaf(x2v, vR2, nR2);
            float i2v = fmaf(y2v, vI2, nI2);
            float rc = fmaf(r1, r2, -i1v * i2v);
            float ic = fmaf(r1, i2v, i1v * r2);
            s2A += rc;
            s2B += ic;
            q2A = fmaf(rc, rc, q2A);
            q2B = fmaf(ic, ic, q2B);
            dA = fmaf(rc, wav, dA);
            dB = fmaf(ic, wbv, dB);
        }
    }

    // Tree B: 6 values, 4-stage segment butterfly
#pragma unroll
    for (int o = 8; o; o >>= 1) {
        s2A += __shfl_xor_sync(0xffffffffu, s2A, o);
        s2B += __shfl_xor_sync(0xffffffffu, s2B, o);
        q2A += __shfl_xor_sync(0xffffffffu, q2A, o);
        q2B += __shfl_xor_sync(0xffffffffu, q2B, o);
        dA  += __shfl_xor_sync(0xffffffffu, dA, o);
        dB  += __shfl_xor_sync(0xffffffffu, dB, o);
    }

    if (sl == 0 && live) {
        float sAr = RS[rr * 2], sBr = RS[rr * 2 + 1];
        float mA = s2A * rD;
        float mB = s2B * rD;
        float invA = rsqrtf(fmaf(-mA, mA, q2A * rD) + 1e-5f);
        float invB = rsqrtf(fmaf(-mB, mB, q2B * rD) + 1e-5f);
        float acc = invA * fmaf(-mA, sAr, dA) + invB * fmaf(-mB, sBr, dB);
        out[e] = 1.f / (1.f + expf(-acc));
    }
}

// ---------------------------------------------------------------------------
extern "C" void kernel_launch(void* const* d_in, const int* in_sizes, int n_in,
                              void* d_out, int out_size) {
    const float* drug_fp   = (const float*)d_in[0];
    const float* drug_init = (const float*)d_in[1];
    const float* x1        = (const float*)d_in[2];
    const float* x2        = (const float*)d_in[3];
    const float* W_fp      = (const float*)d_in[4];
    const float* W_skip    = (const float*)d_in[5];
    const float* wr        = (const float*)d_in[6];
    const float* wi        = (const float*)d_in[7];
    const int*   idx1      = (const int*)d_in[8];
    const int*   idx2      = (const int*)d_in[9];
    const int*   idx3      = (const int*)d_in[10];
    float*       out       = (float*)d_out;
    int E = in_sizes[8];

    float *fpn, *NS, *RS;
    __half *P, *wAB;
    cudaGetSymbolAddress((void**)&fpn, g_fpn);
    cudaGetSymbolAddress((void**)&P,   g_P);
    cudaGetSymbolAddress((void**)&wAB, g_wAB);
    cudaGetSymbolAddress((void**)&NS,  g_NS);
    cudaGetSymbolAddress((void**)&RS,  g_RS);

    // 1) fp_n = elu(LN(drug_fp))
    lnelu512_kernel<<<(NN * 32 + 255) / 256, 256>>>(drug_fp, fpn);

    // 2) pack x1/x2 and relation weights (fp16)
    pack_kernel<<<(NN * DD + 255) / 256, 256>>>(x1, x2, wr, wi, P, wAB);

    // 3) GEMMs -> slots 2/3 of P (fp16)
    dim3 gg((NN + 63) / 64, DD / 64, 2);
    gemm_nt_kernel<<<gg, 256>>>(fpn, W_fp, drug_init, W_skip, P);

    // 4) merged per-node + per-relation sums (one launch)
    stats_kernel<<<((NN + RR) * 32 + 255) / 256, 256>>>(P, wAB, NS, RS);

    // 5) edge phase: two edges per warp
    edge_kernel<<<(E + 15) / 16, 256>>>(P, wAB, NS, RS, idx1, idx2, idx3, out, E);
}

// round 17
// speedup vs baseline: 1.3326x; 1.0954x over previous
#include <cuda_runtime.h>
#include <cuda_fp16.h>
#include <math.h>

#define NN 2000   // nodes
#define HH 512    // hidden
#define DD 256    // embed dim
#define RR 86     // relations

// Scratch
__device__ float  g_fpn[NN * HH];
__device__ __half g_P[NN * 4 * DD];     // per node: [x1 | x2 | xfp | xskip] (fp16)
__device__ __half g_wAB[RR * 2 * DD];   // per relation: [wr-wi | wr+wi] (fp16)
__device__ float  g_NS[NN * 8];         // per node: S[4] (sums of rounded fp16 values)
__device__ float  g_RS[RR * 2];         // per relation: sum(wA), sum(wB)

__device__ __forceinline__ float elu1(float x) {
    return x > 0.f ? x : expm1f(x);
}
__device__ __forceinline__ float sum4(const float4& v) {
    return (v.x + v.y) + (v.z + v.w);
}
__device__ __forceinline__ float sq4(const float4& v) {
    float q = v.x * v.x;
    q = fmaf(v.y, v.y, q);
    q = fmaf(v.z, v.z, q);
    q = fmaf(v.w, v.w, q);
    return q;
}
__device__ __forceinline__ __half2 h2(const float4& r, int k) {
    return reinterpret_cast<const __half2*>(&r)[k];
}
__device__ __forceinline__ void comb4(const float4& ra, const float4& rb,
                                      __half2* o, float& q) {
#pragma unroll
    for (int k = 0; k < 4; ++k) {
        __half2 s = __hadd2(h2(ra, k), h2(rb, k));
        o[k] = s;
        float2 t = __half22float2(s);
        q = fmaf(t.x, t.x, q);
        q = fmaf(t.y, t.y, q);
    }
}
// convert 2 float4 (8 floats) -> float4 of 8 halves; accumulate rounded sum
__device__ __forceinline__ float4 pack8(const float4& a, const float4& b, float& s) {
    __half2 hh[4];
    hh[0] = __floats2half2_rn(a.x, a.y);
    hh[1] = __floats2half2_rn(a.z, a.w);
    hh[2] = __floats2half2_rn(b.x, b.y);
    hh[3] = __floats2half2_rn(b.z, b.w);
#pragma unroll
    for (int k = 0; k < 4; ++k) {
        float2 t = __half22float2(hh[k]);
        s += t.x + t.y;
    }
    return *reinterpret_cast<float4*>(hh);
}

// ---------------------------------------------------------------------------
// Kernel 1: fp_n = elu(LayerNorm(drug_fp)), one warp per row (H=512)
// ---------------------------------------------------------------------------
__global__ void lnelu512_kernel(const float* __restrict__ in, float* __restrict__ out) {
    int gw   = (blockIdx.x * blockDim.x + threadIdx.x) >> 5;
    int lane = threadIdx.x & 31;
    if (gw >= NN) return;
    const float4* p = reinterpret_cast<const float4*>(in + (size_t)gw * HH);
    float4 v[4];
    float s = 0.f, q = 0.f;
#pragma unroll
    for (int i = 0; i < 4; ++i) {
        v[i] = p[lane + 32 * i];
        s += sum4(v[i]);
        q += sq4(v[i]);
    }
#pragma unroll
    for (int o = 16; o; o >>= 1) {
        s += __shfl_xor_sync(0xffffffffu, s, o);
        q += __shfl_xor_sync(0xffffffffu, q, o);
    }
    float m   = s * (1.f / HH);
    float var = fmaf(-m, m, q * (1.f / HH));
    float inv = rsqrtf(var + 1e-5f);
    float4* o4 = reinterpret_cast<float4*>(out + (size_t)gw * HH);
#pragma unroll
    for (int i = 0; i < 4; ++i) {
        float4 y;
        y.x = elu1((v[i].x - m) * inv);
        y.y = elu1((v[i].y - m) * inv);
        y.z = elu1((v[i].z - m) * inv);
        y.w = elu1((v[i].w - m) * inv);
        o4[lane + 32 * i] = y;
    }
}

// ---------------------------------------------------------------------------
// Kernel 2: warp-per-row pack + stats.
// Warps [0, NN): pack x1/x2 -> P slots 0/1, write NS[+0,+1], zero NS[+2,+3].
// Warps [NN, NN+RR): wA=wr-wi, wB=wr+wi -> wAB (fp16), write RS.
// ---------------------------------------------------------------------------
__global__ void pack_kernel(const float* __restrict__ x1, const float* __restrict__ x2,
                            const float* __restrict__ wr, const float* __restrict__ wi,
                            __half* __restrict__ P, __half* __restrict__ wAB,
                            float* __restrict__ NS, float* __restrict__ RS) {
    int gw   = (blockIdx.x * blockDim.x + threadIdx.x) >> 5;
    int lane = threadIdx.x & 31;
    if (gw < NN) {
        const float4* px1 = reinterpret_cast<const float4*>(x1 + (size_t)gw * DD);
        const float4* px2 = reinterpret_cast<const float4*>(x2 + (size_t)gw * DD);
        float4 a0 = px1[2 * lane], a1 = px1[2 * lane + 1];
        float4 b0 = px2[2 * lane], b1 = px2[2 * lane + 1];
        float s0 = 0.f, s1 = 0.f;
        float4 h0 = pack8(a0, a1, s0);   // x1 elems d = 8*lane .. 8*lane+7
        float4 h1 = pack8(b0, b1, s1);   // x2
        float4* prow = reinterpret_cast<float4*>(P + (size_t)gw * (4 * DD));
        prow[lane]      = h0;            // slot 0: float4 index 0..31
        prow[32 + lane] = h1;            // slot 1
#pragma unroll
        for (int o = 16; o; o >>= 1) {
            s0 += __shfl_xor_sync(0xffffffffu, s0, o);
            s1 += __shfl_xor_sync(0xffffffffu, s1, o);
        }
        if (lane == 0) {
            NS[gw * 8 + 0] = s0;
            NS[gw * 8 + 1] = s1;
            NS[gw * 8 + 2] = 0.f;   // accumulated by GEMM epilogue atomics
            NS[gw * 8 + 3] = 0.f;
        }
    } else if (gw < NN + RR) {
        int r = gw - NN;
        const float4* pr = reinterpret_cast<const float4*>(wr + (size_t)r * DD);
        const float4* pi = reinterpret_cast<const float4*>(wi + (size_t)r * DD);
        float4 a0 = pr[2 * lane], a1 = pr[2 * lane + 1];
        float4 b0 = pi[2 * lane], b1 = pi[2 * lane + 1];
        float4 wa0, wa1, wb0, wb1;
        wa0.x = a0.x - b0.x; wa0.y = a0.y - b0.y; wa0.z = a0.z - b0.z; wa0.w = a0.w - b0.w;
        wa1.x = a1.x - b1.x; wa1.y = a1.y - b1.y; wa1.z = a1.z - b1.z; wa1.w = a1.w - b1.w;
        wb0.x = a0.x + b0.x; wb0.y = a0.y + b0.y; wb0.z = a0.z + b0.z; wb0.w = a0.w + b0.w;
        wb1.x = a1.x + b1.x; wb1.y = a1.y + b1.y; wb1.z = a1.z + b1.z; wb1.w = a1.w + b1.w;
        float sA = 0.f, sB = 0.f;
        float4 hA = pack8(wa0, wa1, sA);
        float4 hB = pack8(wb0, wb1, sB);
        float4* wrow = reinterpret_cast<float4*>(wAB + (size_t)r * (2 * DD));
        wrow[lane]      = hA;            // wA: float4 index 0..31
        wrow[32 + lane] = hB;            // wB: 32..63
#pragma unroll
        for (int o = 16; o; o >>= 1) {
            sA += __shfl_xor_sync(0xffffffffu, sA, o);
            sB += __shfl_xor_sync(0xffffffffu, sB, o);
        }
        if (lane == 0) {
            RS[r * 2]     = sA;
            RS[r * 2 + 1] = sB;
        }
    }
}

// ---------------------------------------------------------------------------
// Kernel 3: GEMM C[n,slot,d] = (elu?)(sum_h A[n,h] * W[d,h]) -> fp16 into P.
// Contiguous 4x4 microtile (LDS.128 operand loads); epilogue accumulates
// rounded row-sums into NS[+slot] via one atomicAdd per 16-lane group.
// ---------------------------------------------------------------------------
__global__ void __launch_bounds__(256)
gemm_nt_kernel(const float* __restrict__ A0, const float* __restrict__ W0,
               const float* __restrict__ A1, const float* __restrict__ W1,
               __half* __restrict__ P, float* __restrict__ NS) {
    __shared__ float As[16][68];
    __shared__ float Ws[16][68];
    const float* A = blockIdx.z ? A1 : A0;
    const float* W = blockIdx.z ? W1 : W0;
    int slot = blockIdx.z ? 3 : 2;
    int doElu = blockIdx.z ? 0 : 1;
    int tid = threadIdx.x;
    int tx = tid & 15, ty = tid >> 4;
    int n0 = blockIdx.x * 64, d0 = blockIdx.y * 64;
    float acc[4][4] = {};
    for (int h0 = 0; h0 < HH; h0 += 16) {
#pragma unroll
        for (int i = 0; i < 4; ++i) {
            int idx = tid + i * 256;
            int k = idx & 15, n = idx >> 4;
            int gn = n0 + n;
            As[k][n] = (gn < NN) ? A[(size_t)gn * HH + h0 + k] : 0.f;
            Ws[k][n] = W[(size_t)(d0 + n) * HH + h0 + k];
        }
        __syncthreads();
#pragma unroll
        for (int k = 0; k < 16; ++k) {
            float4 a = *reinterpret_cast<const float4*>(&As[k][ty * 4]);
            float4 b = *reinterpret_cast<const float4*>(&Ws[k][tx * 4]);
            const float* ap = &a.x;
            const float* bp = &b.x;
#pragma unroll
            for (int i = 0; i < 4; ++i)
#pragma unroll
                for (int j = 0; j < 4; ++j)
                    acc[i][j] = fmaf(ap[i], bp[j], acc[i][j]);
        }
        __syncthreads();
    }
#pragma unroll
    for (int i = 0; i < 4; ++i) {
        int n = n0 + ty * 4 + i;
        bool ok = (n < NN);
        float rs = 0.f;
        __half* dst = P + (size_t)n * (4 * DD) + slot * DD + d0 + tx * 4;
#pragma unroll
        for (int j = 0; j < 4; ++j) {
            float v = acc[i][j];
            if (doElu) v = elu1(v);
            __half hv = __float2half(v);
            if (ok) dst[j] = hv;
            rs += __half2float(hv);
        }
        // reduce rs over the 16 tx lanes (low 4 bits of lane id)
#pragma unroll
        for (int o = 1; o < 16; o <<= 1)
            rs += __shfl_xor_sync(0xffffffffu, rs, o);
        if (tx == 0 && ok)
            atomicAdd(&NS[n * 8 + slot], rs);
    }
}

// ---------------------------------------------------------------------------
// Kernel 4: edge phase (R10 configuration — early loads, 3 CTAs/SM).
// TWO edges per warp, 16-lane segments; segment butterflies (offsets 8/4/2/1).
// ---------------------------------------------------------------------------
__global__ void __launch_bounds__(256, 3)
edge_kernel(const __half* __restrict__ Ph, const __half* __restrict__ wABh,
            const float* __restrict__ NS, const float* __restrict__ RS,
            const int* __restrict__ idx1, const int* __restrict__ idx2,
            const int* __restrict__ idx3,
            float* __restrict__ out, int E) {
    int warp = (blockIdx.x * blockDim.x + threadIdx.x) >> 5;
    int lane = threadIdx.x & 31;
    int seg  = lane >> 4;
    int sl   = lane & 15;
    int e = warp * 2 + seg;
    bool live = (e < E);
    int ec = live ? e : (E - 1);

    int i1 = idx1[ec], i2 = idx2[ec], rr = idx3[ec];
    const float4* p1 = reinterpret_cast<const float4*>(Ph) + ((size_t)i1 << 7);
    const float4* p2 = reinterpret_cast<const float4*>(Ph) + ((size_t)i2 << 7);
    const float4* wp = reinterpret_cast<const float4*>(wABh) + ((size_t)rr << 6);

    float4 S1 = *reinterpret_cast<const float4*>(NS + i1 * 8);
    float4 S2 = *reinterpret_cast<const float4*>(NS + i2 * 8);

    // Wave 1: R1 = x1[i1]+xfp[i2], I1 = x2[i1]+xskip[i2]
    __half2 R1h[8], I1h[8], R2h[8], I2h[8];
    float qR1 = 0.f, qI1 = 0.f, qR2 = 0.f, qI2 = 0.f;
    {
        float4 a0l = p1[sl],        a0h = p1[16 + sl];
        float4 b2l = p2[64 + sl],   b2h = p2[80 + sl];
        float4 a1l = p1[32 + sl],   a1h = p1[48 + sl];
        float4 b3l = p2[96 + sl],   b3h = p2[112 + sl];
        comb4(a0l, b2l, R1h,     qR1);
        comb4(a0h, b2h, R1h + 4, qR1);
        comb4(a1l, b3l, I1h,     qI1);
        comb4(a1h, b3h, I1h + 4, qI1);
    }
    // Wave 2: R2 = xskip[i1]+x2[i2], I2 = xfp[i1]+x1[i2]
    {
        float4 a3l = p1[96 + sl],   a3h = p1[112 + sl];
        float4 b1l = p2[32 + sl],   b1h = p2[48 + sl];
        float4 a2l = p1[64 + sl],   a2h = p1[80 + sl];
        float4 b0l = p2[sl],        b0h = p2[16 + sl];
        comb4(a3l, b1l, R2h,     qR2);
        comb4(a3h, b1h, R2h + 4, qR2);
        comb4(a2l, b0l, I2h,     qI2);
        comb4(a2h, b0h, I2h + 4, qI2);
    }

    float4 rwal = wp[sl],      rwah = wp[16 + sl];
    float4 rwbl = wp[32 + sl], rwbh = wp[48 + sl];

    // Tree A: 4 sumsq values, 4-stage segment butterfly
#pragma unroll
    for (int o = 8; o; o >>= 1) {
        qR1 += __shfl_xor_sync(0xffffffffu, qR1, o);
        qI1 += __shfl_xor_sync(0xffffffffu, qI1, o);
        qR2 += __shfl_xor_sync(0xffffffffu, qR2, o);
        qI2 += __shfl_xor_sync(0xffffffffu, qI2, o);
    }

    const float rD = 1.f / DD;
    float mR1 = (S1.x + S2.z) * rD;
    float mI1 = (S1.y + S2.w) * rD;
    float mR2 = (S1.w + S2.y) * rD;
    float mI2 = (S1.z + S2.x) * rD;
    float vR1 = rsqrtf(fmaf(-mR1, mR1, qR1 * rD) + 1e-5f);
    float vI1 = rsqrtf(fmaf(-mI1, mI1, qI1 * rD) + 1e-5f);
    float vR2 = rsqrtf(fmaf(-mR2, mR2, qR2 * rD) + 1e-5f);
    float vI2 = rsqrtf(fmaf(-mI2, mI2, qI2 * rD) + 1e-5f);
    float nR1 = -mR1 * vR1, nI1 = -mI1 * vI1, nR2 = -mR2 * vR2, nI2 = -mI2 * vI2;

    float s2A = 0.f, s2B = 0.f, q2A = 0.f, q2B = 0.f, dA = 0.f, dB = 0.f;
#pragma unroll
    for (int v = 0; v < 8; ++v) {
        float2 f1 = __half22float2(R1h[v]);
        float2 g1 = __half22float2(I1h[v]);
        float2 f2 = __half22float2(R2h[v]);
        float2 g2 = __half22float2(I2h[v]);
        float2 fa = __half22float2((v < 4) ? h2(rwal, v) : h2(rwah, v - 4));
        float2 fb = __half22float2((v < 4) ? h2(rwbl, v) : h2(rwbh, v - 4));
#pragma unroll
        for (int c = 0; c < 2; ++c) {
            float x1v = c ? f1.y : f1.x;
            float y1v = c ? g1.y : g1.x;
            float x2v = c ? f2.y : f2.x;
            float y2v = c ? g2.y : g2.x;
            float wav = c ? fa.y : fa.x;
            float wbv = c ? fb.y : fb.x;
            float r1  = fmaf(x1v, vR1, nR1);
            float i1v = fmaf(y1v, vI1, nI1);
            float r2  = fmaf(x2v, vR2, nR2);
            float i2v = fmaf(y2v, vI2, nI2);
            float rc = fmaf(r1, r2, -i1v * i2v);
            float ic = fmaf(r1, i2v, i1v * r2);
            s2A += rc;
            s2B += ic;
            q2A = fmaf(rc, rc, q2A);
            q2B = fmaf(ic, ic, q2B);
            dA = fmaf(rc, wav, dA);
            dB = fmaf(ic, wbv, dB);
        }
    }

    // Tree B: 6 values, 4-stage segment butterfly
#pragma unroll
    for (int o = 8; o; o >>= 1) {
        s2A += __shfl_xor_sync(0xffffffffu, s2A, o);
        s2B += __shfl_xor_sync(0xffffffffu, s2B, o);
        q2A += __shfl_xor_sync(0xffffffffu, q2A, o);
        q2B += __shfl_xor_sync(0xffffffffu, q2B, o);
        dA  += __shfl_xor_sync(0xffffffffu, dA, o);
        dB  += __shfl_xor_sync(0xffffffffu, dB, o);
    }

    if (sl == 0 && live) {
        float sAr = RS[rr * 2], sBr = RS[rr * 2 + 1];
        float mA = s2A * rD;
        float mB = s2B * rD;
        float invA = rsqrtf(fmaf(-mA, mA, q2A * rD) + 1e-5f);
        float invB = rsqrtf(fmaf(-mB, mB, q2B * rD) + 1e-5f);
        float acc = invA * fmaf(-mA, sAr, dA) + invB * fmaf(-mB, sBr, dB);
        out[e] = 1.f / (1.f + expf(-acc));
    }
}

// ---------------------------------------------------------------------------
extern "C" void kernel_launch(void* const* d_in, const int* in_sizes, int n_in,
                              void* d_out, int out_size) {
    const float* drug_fp   = (const float*)d_in[0];
    const float* drug_init = (const float*)d_in[1];
    const float* x1        = (const float*)d_in[2];
    const float* x2        = (const float*)d_in[3];
    const float* W_fp      = (const float*)d_in[4];
    const float* W_skip    = (const float*)d_in[5];
    const float* wr        = (const float*)d_in[6];
    const float* wi        = (const float*)d_in[7];
    const int*   idx1      = (const int*)d_in[8];
    const int*   idx2      = (const int*)d_in[9];
    const int*   idx3      = (const int*)d_in[10];
    float*       out       = (float*)d_out;
    int E = in_sizes[8];

    float *fpn, *NS, *RS;
    __half *P, *wAB;
    cudaGetSymbolAddress((void**)&fpn, g_fpn);
    cudaGetSymbolAddress((void**)&P,   g_P);
    cudaGetSymbolAddress((void**)&wAB, g_wAB);
    cudaGetSymbolAddress((void**)&NS,  g_NS);
    cudaGetSymbolAddress((void**)&RS,  g_RS);

    // 1) fp_n = elu(LN(drug_fp))
    lnelu512_kernel<<<(NN * 32 + 255) / 256, 256>>>(drug_fp, fpn);

    // 2) warp-per-row pack + stats (x1/x2 -> P, weights -> wAB, NS[0,1], RS; zero NS[2,3])
    pack_kernel<<<((NN + RR) * 32 + 255) / 256, 256>>>(x1, x2, wr, wi, P, wAB, NS, RS);

    // 3) GEMMs -> slots 2/3 of P + NS[2,3] via epilogue atomics
    dim3 gg((NN + 63) / 64, DD / 64, 2);
    gemm_nt_kernel<<<gg, 256>>>(fpn, W_fp, drug_init, W_skip, P, NS);

    // 4) edge phase: two edges per warp
    edge_kernel<<<(E + 15) / 16, 256>>>(P, wAB, NS, RS, idx1, idx2, idx3, out, E);
}